// round 6
// baseline (speedup 1.0000x reference)
#include <cuda_runtime.h>
#include <cstdint>

typedef unsigned long long u64;

#define T_STEPS 480000
#define PF 4

// Compiler-only ordering fence. With a single fully-convergent warp, the
// shared-memory pipeline enforces same-warp STS->LDS ordering in HW; we only
// need to stop nvcc/ptxas from reordering across the communication point.
#define SMEM_FENCE() asm volatile("" ::: "memory")

// Per-step packed params (PF steps of zero padding at the end):
//   A = {K, R01, R11, R10},  B = {R12*v, R02*v, dr, 0}
// where K = R00 + R01*R10_prev  (folds the b1 recurrence into a single FMA on dpb)
__device__ float g_params[(T_STEPS + PF) * 8];

// ---------------------------------------------------------------------------
// Parallel precompute of all carry-independent WDF coefficients.
// ---------------------------------------------------------------------------
__global__ void ndc_precompute(const float* __restrict__ v_in,
                               const float* __restrict__ vs_r,
                               const float* __restrict__ fs) {
    int t = blockIdx.x * blockDim.x + threadIdx.x;
    if (t >= T_STEPS + PF) return;
    float4 A, B;
    if (t >= T_STEPS) {
        A = make_float4(0.f, 0.f, 0.f, 0.f);
        B = A;
    } else {
        const float C1 = 4.7e-9f;
        float f   = fs[t];
        float vr  = vs_r[t];
        float c1r = 1.0f / (2.0f * C1 * f);
        float r0  = c1r * vr / (c1r + vr);
        float g0  = 1.0f / r0, g1 = 1.0f / c1r, g2 = 1.0f / vr;
        float s   = g0 + g1 + g2;
        float P0  = 2.0f * g0 / s, P1 = 2.0f * g1 / s, P2 = 2.0f * g2 / s;
        float R00 = P0 - 1.0f, R01 = P1, R02 = P2;
        float R10 = P0, R11 = P1 - 1.0f, R12 = P2;
        float R10p = 0.0f;
        if (t > 0) {
            float fp = fs[t - 1], vp = vs_r[t - 1];
            float c1p = 1.0f / (2.0f * C1 * fp);
            float rp  = c1p * vp / (c1p + vp);
            float h0 = 1.0f / rp, h1 = 1.0f / c1p, h2 = 1.0f / vp;
            float sp = h0 + h1 + h2;
            R10p = 2.0f * h0 / sp;
        }
        float v = v_in[t];
        float K = fmaf(R01, R10p, R00);
        A = make_float4(K, R01, R11, R10);
        B = make_float4(R12 * v, R02 * v, r0 / 3000.0f, 0.0f);
    }
    float4* p = reinterpret_cast<float4*>(g_params);
    p[2 * t]     = A;
    p[2 * t + 1] = B;
}

// ---------------------------------------------------------------------------
// Packed f32x2 helpers (Blackwell FFMA2 path)
// ---------------------------------------------------------------------------
__device__ __forceinline__ u64 ffma2(u64 a, u64 b, u64 c) {
    u64 d;
    asm("fma.rn.f32x2 %0, %1, %2, %3;" : "=l"(d) : "l"(a), "l"(b), "l"(c));
    return d;
}
__device__ __forceinline__ u64 fadd2(u64 a, u64 b) {
    u64 d;
    asm("add.rn.f32x2 %0, %1, %2;" : "=l"(d) : "l"(a), "l"(b));
    return d;
}
__device__ __forceinline__ float hsum2(u64 a) {
    return __uint_as_float((unsigned)a) + __uint_as_float((unsigned)(a >> 32));
}

// 32x32 matvec: lane holds one row (16 packed f32x2 weights); h broadcast via
// smem. Bias folded into accumulator init (low half of a0).
__device__ __forceinline__ float layer32(const float* sh, const u64* w, float bias) {
    const ulonglong2* h = reinterpret_cast<const ulonglong2*>(sh);
    u64 a0 = (u64)__float_as_uint(bias);   // {bias, 0}
    u64 a1 = 0ull, a2 = 0ull, a3 = 0ull;
#pragma unroll
    for (int k = 0; k < 8; k += 2) {
        ulonglong2 h0 = h[k];
        ulonglong2 h1 = h[k + 1];
        a0 = ffma2(w[2 * k + 0], h0.x, a0);
        a1 = ffma2(w[2 * k + 1], h0.y, a1);
        a2 = ffma2(w[2 * k + 2], h1.x, a2);
        a3 = ffma2(w[2 * k + 3], h1.y, a3);
    }
    return hsum2(fadd2(fadd2(a0, a1), fadd2(a2, a3)));
}

// ---------------------------------------------------------------------------
// Sequential scan: single warp, warp-synchronous smem communication (no
// BAR/WARPSYNC — HW same-warp smem ordering + compiler fences only).
// ---------------------------------------------------------------------------
__global__ void __launch_bounds__(32, 1) ndc_scan(
    const float* __restrict__ W_in, const float* __restrict__ b_in,
    const float* __restrict__ W_h,  const float* __restrict__ b_h,
    const float* __restrict__ W_out, const float* __restrict__ b_out,
    float* __restrict__ out)
{
    __shared__ __align__(16) float sh1[32];
    __shared__ __align__(16) float sh2[32];
    __shared__ __align__(16) float sred[32];
    const int lane = threadIdx.x;

    // Per-lane weights
    float win0 = W_in[2 * lane];
    float win1 = W_in[2 * lane + 1];
    float bin  = b_in[lane];
    float bh1  = b_h[lane];
    float bh2  = b_h[32 + lane];
    float wout = W_out[lane];
    float bout = b_out[0];

    u64 w1[16], w2[16];
    {
        const ulonglong2* r1 = reinterpret_cast<const ulonglong2*>(W_h + lane * 32);
        const ulonglong2* r2 = reinterpret_cast<const ulonglong2*>(W_h + 1024 + lane * 32);
#pragma unroll
        for (int k = 0; k < 8; ++k) {
            ulonglong2 x = r1[k]; w1[2 * k] = x.x; w1[2 * k + 1] = x.y;
            ulonglong2 y = r2[k]; w2[2 * k] = y.x; w2[2 * k + 1] = y.y;
        }
    }

    const float4* Pp = reinterpret_cast<const float4*>(g_params);
    float4 bufA[PF], bufB[PF];
#pragma unroll
    for (int k = 0; k < PF; ++k) { bufA[k] = Pp[2 * k]; bufB[k] = Pp[2 * k + 1]; }

    // Recurrence state
    float dpb    = 0.0f;   // dpb_{t-1}
    float b1tail = 0.0f;   // R11_{t-1}*b1_{t-2} + R12v_{t-1}
    float R10p   = 0.0f;   // R10_{t-1}

    // Prepared (one step ahead) values for step 0
    float Kc = bufA[0].x;                     // K_0
    float uc = bufB[0].y;                     // u_0 = R02v_0  (b1tail_{-1} = 0)
    float ci = fmaf(win1, bufB[0].z, bin);
    float g  = fmaf(win0, uc, ci);
    float wK = win0 * Kc;

    for (int t = 0; t < T_STEPS; t += PF) {
#pragma unroll
        for (int u = 0; u < PF; ++u) {
            float4 A = bufA[u];
            float4 B = bufB[u];
            int nu = (u + 1) & (PF - 1);
            float4 nA = bufA[nu];
            float4 nB = bufB[nu];
            // refresh this slot (params are zero-padded past T_STEPS)
            int tp = t + u + PF;
            bufA[u] = Pp[2 * tp];
            bufB[u] = Pp[2 * tp + 1];

            // ---- critical path start: dpb -> h in 2 ops ----
            float h = fmaxf(fmaf(wK, dpb, g), 0.0f);
            sh1[lane] = h;
            SMEM_FENCE();   // warp-synchronous: HW orders same-warp STS->LDS

            // ---- scalar glue for step t+u and prep for t+u+1 (off-path) ----
            float dpa  = fmaf(Kc, dpb, uc);            // dp_a (output only)
            float b1f  = fmaf(R10p, dpb, b1tail);      // b1_{t-1}
            b1tail     = fmaf(A.z, b1f, B.x);          // b1tail_t
            R10p       = A.w;
            uc         = fmaf(nA.y, b1tail, nB.y);     // u_{t+1}
            Kc         = nA.x;
            float cin  = fmaf(win1, nB.z, bin);
            g          = fmaf(win0, uc, cin);
            wK         = win0 * Kc;

            // ---- hidden layer 1 ----
            float hh = fmaxf(layer32(sh1, w1, bh1), 0.0f);
            sh2[lane] = hh;
            SMEM_FENCE();

            // ---- hidden layer 2 + output weight ----
            float h3 = fmaxf(layer32(sh2, w2, bh2), 0.0f);
            sred[lane] = wout * h3;
            SMEM_FENCE();

            // ---- 32-way reduce, redundantly in all lanes (bout folded) ----
            const ulonglong2* rp = reinterpret_cast<const ulonglong2*>(sred);
            u64 s0 = (u64)__float_as_uint(bout);   // {bout, 0}
            u64 s1 = 0ull, s2 = 0ull, s3 = 0ull;
#pragma unroll
            for (int k = 0; k < 8; k += 2) {
                ulonglong2 x = rp[k], y = rp[k + 1];
                s0 = fadd2(s0, x.x); s1 = fadd2(s1, x.y);
                s2 = fadd2(s2, y.x); s3 = fadd2(s3, y.y);
            }
            float dpbn = hsum2(fadd2(fadd2(s0, s1), fadd2(s2, s3)));

            if (lane == 0) out[t + u] = 0.5f * (dpa + dpbn);
            dpb = dpbn;
        }
    }
}

extern "C" void kernel_launch(void* const* d_in, const int* in_sizes, int n_in,
                              void* d_out, int out_size) {
    const float* v_in  = (const float*)d_in[0];
    const float* vs_r  = (const float*)d_in[1];
    const float* fs    = (const float*)d_in[2];
    const float* W_in  = (const float*)d_in[3];
    const float* b_in  = (const float*)d_in[4];
    const float* W_h   = (const float*)d_in[5];
    const float* b_h   = (const float*)d_in[6];
    const float* W_out = (const float*)d_in[7];
    const float* b_out = (const float*)d_in[8];
    float* out = (float*)d_out;

    ndc_precompute<<<(T_STEPS + PF + 255) / 256, 256>>>(v_in, vs_r, fs);
    ndc_scan<<<1, 32>>>(W_in, b_in, W_h, b_h, W_out, b_out, out);
}

// round 7
// speedup vs baseline: 1.1103x; 1.1103x over previous
#include <cuda_runtime.h>
#include <cstdint>

typedef unsigned long long u64;

#define T_STEPS 480000
#define PF 4

// Per-step packed params (PF steps of zero padding at the end):
//   A = {K, R01, R11, R10},  B = {R12*v, R02*v, dr, 0}
// where K = R00 + R01*R10_prev  (folds the b1 recurrence into a single FMA on dpb)
__device__ float g_params[(T_STEPS + PF) * 8];

// ---------------------------------------------------------------------------
// Parallel precompute of all carry-independent WDF coefficients.
// ---------------------------------------------------------------------------
__global__ void ndc_precompute(const float* __restrict__ v_in,
                               const float* __restrict__ vs_r,
                               const float* __restrict__ fs) {
    int t = blockIdx.x * blockDim.x + threadIdx.x;
    if (t >= T_STEPS + PF) return;
    float4 A, B;
    if (t >= T_STEPS) {
        A = make_float4(0.f, 0.f, 0.f, 0.f);
        B = A;
    } else {
        const float C1 = 4.7e-9f;
        float f   = fs[t];
        float vr  = vs_r[t];
        float c1r = 1.0f / (2.0f * C1 * f);
        float r0  = c1r * vr / (c1r + vr);
        float g0  = 1.0f / r0, g1 = 1.0f / c1r, g2 = 1.0f / vr;
        float s   = g0 + g1 + g2;
        float P0  = 2.0f * g0 / s, P1 = 2.0f * g1 / s, P2 = 2.0f * g2 / s;
        float R00 = P0 - 1.0f, R01 = P1, R02 = P2;
        float R10 = P0, R11 = P1 - 1.0f, R12 = P2;
        float R10p = 0.0f;
        if (t > 0) {
            float fp = fs[t - 1], vp = vs_r[t - 1];
            float c1p = 1.0f / (2.0f * C1 * fp);
            float rp  = c1p * vp / (c1p + vp);
            float h0 = 1.0f / rp, h1 = 1.0f / c1p, h2 = 1.0f / vp;
            float sp = h0 + h1 + h2;
            R10p = 2.0f * h0 / sp;
        }
        float v = v_in[t];
        float K = fmaf(R01, R10p, R00);
        A = make_float4(K, R01, R11, R10);
        B = make_float4(R12 * v, R02 * v, r0 / 3000.0f, 0.0f);
    }
    float4* p = reinterpret_cast<float4*>(g_params);
    p[2 * t]     = A;
    p[2 * t + 1] = B;
}

// ---------------------------------------------------------------------------
// Packed f32x2 helpers (Blackwell FFMA2 path)
// ---------------------------------------------------------------------------
__device__ __forceinline__ u64 ffma2(u64 a, u64 b, u64 c) {
    u64 d;
    asm("fma.rn.f32x2 %0, %1, %2, %3;" : "=l"(d) : "l"(a), "l"(b), "l"(c));
    return d;
}
__device__ __forceinline__ u64 fadd2(u64 a, u64 b) {
    u64 d;
    asm("add.rn.f32x2 %0, %1, %2;" : "=l"(d) : "l"(a), "l"(b));
    return d;
}
__device__ __forceinline__ float hsum2(u64 a) {
    return __uint_as_float((unsigned)a) + __uint_as_float((unsigned)(a >> 32));
}

// 32x32 matvec: lane holds one row (16 packed f32x2 weights); h broadcast via
// smem. Bias folded into accumulator init (low half of a0).
__device__ __forceinline__ float layer32(const float* sh, const u64* w, float bias) {
    const ulonglong2* h = reinterpret_cast<const ulonglong2*>(sh);
    u64 a0 = (u64)__float_as_uint(bias);   // {bias, 0}
    u64 a1 = 0ull, a2 = 0ull, a3 = 0ull;
#pragma unroll
    for (int k = 0; k < 8; k += 2) {
        ulonglong2 h0 = h[k];
        ulonglong2 h1 = h[k + 1];
        a0 = ffma2(w[2 * k + 0], h0.x, a0);
        a1 = ffma2(w[2 * k + 1], h0.y, a1);
        a2 = ffma2(w[2 * k + 2], h1.x, a2);
        a3 = ffma2(w[2 * k + 3], h1.y, a3);
    }
    return hsum2(fadd2(fadd2(a0, a1), fadd2(a2, a3)));
}

// ---------------------------------------------------------------------------
// Sequential scan: single warp. Branch-free hot loop: output is computed
// redundantly in all lanes and stored unconditionally (same-address warp
// store), batched as one STG.128 per PF=4 steps.
// ---------------------------------------------------------------------------
__global__ void __launch_bounds__(32, 1) ndc_scan(
    const float* __restrict__ W_in, const float* __restrict__ b_in,
    const float* __restrict__ W_h,  const float* __restrict__ b_h,
    const float* __restrict__ W_out, const float* __restrict__ b_out,
    float* __restrict__ out)
{
    __shared__ __align__(16) float sh1[32];
    __shared__ __align__(16) float sh2[32];
    __shared__ __align__(16) float sred[32];
    const int lane = threadIdx.x;

    // Per-lane weights
    float win0 = W_in[2 * lane];
    float win1 = W_in[2 * lane + 1];
    float bin  = b_in[lane];
    float bh1  = b_h[lane];
    float bh2  = b_h[32 + lane];
    float wout = W_out[lane];
    float bout = b_out[0];

    u64 w1[16], w2[16];
    {
        const ulonglong2* r1 = reinterpret_cast<const ulonglong2*>(W_h + lane * 32);
        const ulonglong2* r2 = reinterpret_cast<const ulonglong2*>(W_h + 1024 + lane * 32);
#pragma unroll
        for (int k = 0; k < 8; ++k) {
            ulonglong2 x = r1[k]; w1[2 * k] = x.x; w1[2 * k + 1] = x.y;
            ulonglong2 y = r2[k]; w2[2 * k] = y.x; w2[2 * k + 1] = y.y;
        }
    }

    const float4* Pp = reinterpret_cast<const float4*>(g_params);
    float4 bufA[PF], bufB[PF];
#pragma unroll
    for (int k = 0; k < PF; ++k) { bufA[k] = Pp[2 * k]; bufB[k] = Pp[2 * k + 1]; }

    // Recurrence state
    float dpb    = 0.0f;   // dpb_{t-1}
    float b1tail = 0.0f;   // R11_{t-1}*b1_{t-2} + R12v_{t-1}
    float R10p   = 0.0f;   // R10_{t-1}

    // Prepared (one step ahead) values for step 0
    float Kc = bufA[0].x;                     // K_0
    float uc = bufB[0].y;                     // u_0 = R02v_0  (b1tail_{-1} = 0)
    float ci = fmaf(win1, bufB[0].z, bin);
    float g  = fmaf(win0, uc, ci);
    float wK = win0 * Kc;

    for (int t = 0; t < T_STEPS; t += PF) {
        float4 ovec;   // 4 outputs, one STG.128 per PF group
#pragma unroll
        for (int u = 0; u < PF; ++u) {
            float4 A = bufA[u];
            float4 B = bufB[u];
            int nu = (u + 1) & (PF - 1);
            float4 nA = bufA[nu];
            float4 nB = bufB[nu];
            // refresh this slot (params are zero-padded past T_STEPS)
            int tp = t + u + PF;
            bufA[u] = Pp[2 * tp];
            bufB[u] = Pp[2 * tp + 1];

            // ---- critical path start: dpb -> h in 2 ops ----
            float h = fmaxf(fmaf(wK, dpb, g), 0.0f);
            sh1[lane] = h;
            __syncthreads();   // nw=1 BAR: cheap, deferred-blocking

            // ---- scalar glue for step t+u and prep for t+u+1 (off-path) ----
            float dpa  = fmaf(Kc, dpb, uc);            // dp_a (output only)
            float b1f  = fmaf(R10p, dpb, b1tail);      // b1_{t-1}
            b1tail     = fmaf(A.z, b1f, B.x);          // b1tail_t
            R10p       = A.w;
            uc         = fmaf(nA.y, b1tail, nB.y);     // u_{t+1}
            Kc         = nA.x;
            float cin  = fmaf(win1, nB.z, bin);
            g          = fmaf(win0, uc, cin);
            wK         = win0 * Kc;

            // ---- hidden layer 1 ----
            float hh = fmaxf(layer32(sh1, w1, bh1), 0.0f);
            sh2[lane] = hh;
            __syncthreads();

            // ---- hidden layer 2 + output weight ----
            float h3 = fmaxf(layer32(sh2, w2, bh2), 0.0f);
            sred[lane] = wout * h3;
            __syncthreads();

            // ---- 32-way reduce, redundantly in all lanes (bout folded) ----
            const ulonglong2* rp = reinterpret_cast<const ulonglong2*>(sred);
            u64 s0 = (u64)__float_as_uint(bout);   // {bout, 0}
            u64 s1 = 0ull, s2 = 0ull, s3 = 0ull;
#pragma unroll
            for (int k = 0; k < 8; k += 2) {
                ulonglong2 x = rp[k], y = rp[k + 1];
                s0 = fadd2(s0, x.x); s1 = fadd2(s1, x.y);
                s2 = fadd2(s2, y.x); s3 = fadd2(s3, y.y);
            }
            float dpbn = hsum2(fadd2(fadd2(s0, s1), fadd2(s2, s3)));

            // branch-free output accumulate (u is compile-time in the unroll)
            float oval = 0.5f * (dpa + dpbn);
            if (u == 0) ovec.x = oval;
            if (u == 1) ovec.y = oval;
            if (u == 2) ovec.z = oval;
            if (u == 3) ovec.w = oval;

            dpb = dpbn;
        }
        // all lanes store the identical float4 to the same address: no branch,
        // coalesces to a single transaction.
        *reinterpret_cast<float4*>(out + t) = ovec;
    }
}

extern "C" void kernel_launch(void* const* d_in, const int* in_sizes, int n_in,
                              void* d_out, int out_size) {
    const float* v_in  = (const float*)d_in[0];
    const float* vs_r  = (const float*)d_in[1];
    const float* fs    = (const float*)d_in[2];
    const float* W_in  = (const float*)d_in[3];
    const float* b_in  = (const float*)d_in[4];
    const float* W_h   = (const float*)d_in[5];
    const float* b_h   = (const float*)d_in[6];
    const float* W_out = (const float*)d_in[7];
    const float* b_out = (const float*)d_in[8];
    float* out = (float*)d_out;

    ndc_precompute<<<(T_STEPS + PF + 255) / 256, 256>>>(v_in, vs_r, fs);
    ndc_scan<<<1, 32>>>(W_in, b_in, W_h, b_h, W_out, b_out, out);
}

// round 8
// speedup vs baseline: 1.1161x; 1.0052x over previous
#include <cuda_runtime.h>
#include <cstdint>

typedef unsigned long long u64;

#define T_STEPS 480000
#define PF 4

// Per-step packed params (PF steps of zero padding at the end):
//   A = {K, R01, R11, R10},  B = {R12*v, R02*v, dr, 0}
// where K = R00 + R01*R10_prev  (folds the b1 recurrence into a single FMA on dpb)
__device__ float g_params[(T_STEPS + PF) * 8];

// ---------------------------------------------------------------------------
// Parallel precompute of all carry-independent WDF coefficients.
// ---------------------------------------------------------------------------
__global__ void ndc_precompute(const float* __restrict__ v_in,
                               const float* __restrict__ vs_r,
                               const float* __restrict__ fs) {
    int t = blockIdx.x * blockDim.x + threadIdx.x;
    if (t >= T_STEPS + PF) return;
    float4 A, B;
    if (t >= T_STEPS) {
        A = make_float4(0.f, 0.f, 0.f, 0.f);
        B = A;
    } else {
        const float C1 = 4.7e-9f;
        float f   = fs[t];
        float vr  = vs_r[t];
        float c1r = 1.0f / (2.0f * C1 * f);
        float r0  = c1r * vr / (c1r + vr);
        float g0  = 1.0f / r0, g1 = 1.0f / c1r, g2 = 1.0f / vr;
        float s   = g0 + g1 + g2;
        float P0  = 2.0f * g0 / s, P1 = 2.0f * g1 / s, P2 = 2.0f * g2 / s;
        float R00 = P0 - 1.0f, R01 = P1, R02 = P2;
        float R10 = P0, R11 = P1 - 1.0f, R12 = P2;
        float R10p = 0.0f;
        if (t > 0) {
            float fp = fs[t - 1], vp = vs_r[t - 1];
            float c1p = 1.0f / (2.0f * C1 * fp);
            float rp  = c1p * vp / (c1p + vp);
            float h0 = 1.0f / rp, h1 = 1.0f / c1p, h2 = 1.0f / vp;
            float sp = h0 + h1 + h2;
            R10p = 2.0f * h0 / sp;
        }
        float v = v_in[t];
        float K = fmaf(R01, R10p, R00);
        A = make_float4(K, R01, R11, R10);
        B = make_float4(R12 * v, R02 * v, r0 / 3000.0f, 0.0f);
    }
    float4* p = reinterpret_cast<float4*>(g_params);
    p[2 * t]     = A;
    p[2 * t + 1] = B;
}

// ---------------------------------------------------------------------------
// Packed f32x2 helpers (Blackwell FFMA2 path)
// ---------------------------------------------------------------------------
__device__ __forceinline__ u64 ffma2(u64 a, u64 b, u64 c) {
    u64 d;
    asm("fma.rn.f32x2 %0, %1, %2, %3;" : "=l"(d) : "l"(a), "l"(b), "l"(c));
    return d;
}
__device__ __forceinline__ u64 fadd2(u64 a, u64 b) {
    u64 d;
    asm("add.rn.f32x2 %0, %1, %2;" : "=l"(d) : "l"(a), "l"(b));
    return d;
}
__device__ __forceinline__ float hsum2(u64 a) {
    return __uint_as_float((unsigned)a) + __uint_as_float((unsigned)(a >> 32));
}

// 32x32 matvec: lane holds one row (16 packed f32x2 weights); h broadcast via
// smem. Bias folded into accumulator init (low half of a0).
__device__ __forceinline__ float layer32(const float* sh, const u64* w, float bias) {
    const ulonglong2* h = reinterpret_cast<const ulonglong2*>(sh);
    u64 a0 = (u64)__float_as_uint(bias);   // {bias, 0}
    u64 a1 = 0ull, a2 = 0ull, a3 = 0ull;
#pragma unroll
    for (int k = 0; k < 8; k += 2) {
        ulonglong2 h0 = h[k];
        ulonglong2 h1 = h[k + 1];
        a0 = ffma2(w[2 * k + 0], h0.x, a0);
        a1 = ffma2(w[2 * k + 1], h0.y, a1);
        a2 = ffma2(w[2 * k + 2], h1.x, a2);
        a3 = ffma2(w[2 * k + 3], h1.y, a3);
    }
    return hsum2(fadd2(fadd2(a0, a1), fadd2(a2, a3)));
}

// ---------------------------------------------------------------------------
// Sequential scan, single warp. Key scheduling rule: between every STS and its
// barrier we place independent scalar work, so the STS SMEM-commit latency
// (no store-forwarding on sm_103a) drains in the shadow of useful issue.
// ---------------------------------------------------------------------------
__global__ void __launch_bounds__(32, 1) ndc_scan(
    const float* __restrict__ W_in, const float* __restrict__ b_in,
    const float* __restrict__ W_h,  const float* __restrict__ b_h,
    const float* __restrict__ W_out, const float* __restrict__ b_out,
    float* __restrict__ out)
{
    __shared__ __align__(16) float sh1[32];
    __shared__ __align__(16) float sh2[32];
    __shared__ __align__(16) float sred[32];
    const int lane = threadIdx.x;

    // Per-lane weights
    float win0 = W_in[2 * lane];
    float win1 = W_in[2 * lane + 1];
    float bin  = b_in[lane];
    float bh1  = b_h[lane];
    float bh2  = b_h[32 + lane];
    float wout = W_out[lane];
    float bout = b_out[0];

    u64 w1[16], w2[16];
    {
        const ulonglong2* r1 = reinterpret_cast<const ulonglong2*>(W_h + lane * 32);
        const ulonglong2* r2 = reinterpret_cast<const ulonglong2*>(W_h + 1024 + lane * 32);
#pragma unroll
        for (int k = 0; k < 8; ++k) {
            ulonglong2 x = r1[k]; w1[2 * k] = x.x; w1[2 * k + 1] = x.y;
            ulonglong2 y = r2[k]; w2[2 * k] = y.x; w2[2 * k + 1] = y.y;
        }
    }

    const float4* Pp = reinterpret_cast<const float4*>(g_params);
    float4 bufA[PF], bufB[PF];
#pragma unroll
    for (int k = 0; k < PF; ++k) { bufA[k] = Pp[2 * k]; bufB[k] = Pp[2 * k + 1]; }

    // Recurrence state
    float dpb    = 0.0f;   // dpb_{t-1}
    float b1tail = 0.0f;   // R11_{t-1}*b1_{t-2} + R12v_{t-1}
    float R10p   = 0.0f;   // R10_{t-1}

    // Prepared (one step ahead) values for step 0
    float Kc = bufA[0].x;                     // K_0
    float uc = bufB[0].y;                     // u_0 = R02v_0  (b1tail_{-1} = 0)
    float ci = fmaf(win1, bufB[0].z, bin);
    float g  = fmaf(win0, uc, ci);
    float wK = win0 * Kc;

    for (int t = 0; t < T_STEPS; t += PF) {
        float4 ovec;
#pragma unroll
        for (int u = 0; u < PF; ++u) {
            float4 A = bufA[u];
            float4 B = bufB[u];
            int nu = (u + 1) & (PF - 1);
            float4 nA = bufA[nu];
            float4 nB = bufB[nu];

            // ================= round 1: input layer =================
            float h = fmaxf(fmaf(wK, dpb, g), 0.0f);
            sh1[lane] = h;
            // --- STS-drain shadow: carry-recurrence glue (independent) ---
            float dpa  = fmaf(Kc, dpb, uc);            // dp_a for output
            float hdpa = 0.5f * dpa;
            float b1f  = fmaf(R10p, dpb, b1tail);      // b1_{t-1}
            b1tail     = fmaf(A.z, b1f, B.x);          // b1tail_t
            R10p       = A.w;
            __syncthreads();

            // ================= round 2: hidden layer 1 =================
            float hh = fmaxf(layer32(sh1, w1, bh1), 0.0f);
            sh2[lane] = hh;
            // --- STS-drain shadow: next-step prep + param prefetch ---
            uc         = fmaf(nA.y, b1tail, nB.y);     // u_{t+1}
            Kc         = nA.x;
            float cin  = fmaf(win1, nB.z, bin);
            g          = fmaf(win0, uc, cin);
            wK         = win0 * Kc;
            int tp = t + u + PF;                       // refresh this slot
            bufA[u] = Pp[2 * tp];
            bufB[u] = Pp[2 * tp + 1];
            __syncthreads();

            // ================= round 3: hidden layer 2 + reduce =================
            float h3 = fmaxf(layer32(sh2, w2, bh2), 0.0f);
            sred[lane] = wout * h3;
            // --- STS-drain shadow: previous group's store already issued;
            //     pack half of the output now (dpa part) ---
            // (hdpa computed above; nothing else independent — short shadow)
            __syncthreads();

            const ulonglong2* rp = reinterpret_cast<const ulonglong2*>(sred);
            u64 s0 = (u64)__float_as_uint(bout);   // {bout, 0}
            u64 s1 = 0ull, s2 = 0ull, s3 = 0ull;
#pragma unroll
            for (int k = 0; k < 8; k += 2) {
                ulonglong2 x = rp[k], y = rp[k + 1];
                s0 = fadd2(s0, x.x); s1 = fadd2(s1, x.y);
                s2 = fadd2(s2, y.x); s3 = fadd2(s3, y.y);
            }
            float dpbn = hsum2(fadd2(fadd2(s0, s1), fadd2(s2, s3)));

            float oval = fmaf(0.5f, dpbn, hdpa);
            if (u == 0) ovec.x = oval;
            if (u == 1) ovec.y = oval;
            if (u == 2) ovec.z = oval;
            if (u == 3) ovec.w = oval;

            dpb = dpbn;
        }
        // all lanes store the identical float4 to the same address (coalesces
        // to one transaction, no branch).
        *reinterpret_cast<float4*>(out + t) = ovec;
    }
}

extern "C" void kernel_launch(void* const* d_in, const int* in_sizes, int n_in,
                              void* d_out, int out_size) {
    const float* v_in  = (const float*)d_in[0];
    const float* vs_r  = (const float*)d_in[1];
    const float* fs    = (const float*)d_in[2];
    const float* W_in  = (const float*)d_in[3];
    const float* b_in  = (const float*)d_in[4];
    const float* W_h   = (const float*)d_in[5];
    const float* b_h   = (const float*)d_in[6];
    const float* W_out = (const float*)d_in[7];
    const float* b_out = (const float*)d_in[8];
    float* out = (float*)d_out;

    ndc_precompute<<<(T_STEPS + PF + 255) / 256, 256>>>(v_in, vs_r, fs);
    ndc_scan<<<1, 32>>>(W_in, b_in, W_h, b_h, W_out, b_out, out);
}